// round 3
// baseline (speedup 1.0000x reference)
#include <cuda_runtime.h>
#include <cstdint>
#include <cstddef>

#define N_NODES 8192
#define DIM 512

// Scratch (allocation-free: __device__ globals)
__device__ float g_xT[(size_t)DIM * N_NODES];   // x transposed: [DIM, N_NODES]
__device__ float g_agg[(size_t)N_NODES * DIM];  // adj @ x

// ---------------- config ----------------
constexpr int BM = 128;
constexpr int BN = 256;
constexpr int BK = 32;
constexpr int NSTAGE = 3;
constexpr int THREADS = 512;              // 16 warps: 4 (M) x 4 (N), warp tile 32x64
constexpr int AROW = BK + 4;              // 36 floats/row pad -> conflict-free frag LDS
constexpr int A_ELEMS = BM * AROW;        // 4608 floats
constexpr int B_ELEMS = BN * AROW;        // 9216 floats
constexpr int STAGE_ELEMS = A_ELEMS + B_ELEMS;
constexpr size_t SMEM_BYTES = (size_t)NSTAGE * STAGE_ELEMS * sizeof(float); // 162 KB

// ---------------- helpers ----------------
__device__ __forceinline__ uint32_t smem_u32(const void* p) {
    uint32_t a;
    asm("{ .reg .u64 t; cvta.to.shared.u64 t, %1; cvt.u32.u64 %0, t; }" : "=r"(a) : "l"(p));
    return a;
}
// fp32 -> tf32 round-to-nearest (zero-mean error; truncation would bias ~1e-3 and fail)
__device__ __forceinline__ uint32_t f2tf(float f) {
    uint32_t u;
    asm("cvt.rna.tf32.f32 %0, %1;" : "=r"(u) : "f"(f));
    return u;
}
__device__ __forceinline__ void cp16(uint32_t dst, const float* src) {
    asm volatile("cp.async.cg.shared.global [%0], [%1], 16;" :: "r"(dst), "l"(src));
}
__device__ __forceinline__ void mma_tf32(float* d, const uint32_t* a, const uint32_t* b) {
    asm volatile(
        "mma.sync.aligned.m16n8k8.row.col.f32.tf32.tf32.f32 "
        "{%0,%1,%2,%3}, {%4,%5,%6,%7}, {%8,%9}, {%0,%1,%2,%3};"
        : "+f"(d[0]), "+f"(d[1]), "+f"(d[2]), "+f"(d[3])
        : "r"(a[0]), "r"(a[1]), "r"(a[2]), "r"(a[3]), "r"(b[0]), "r"(b[1]));
}

// ---------------- TF32 GEMM: C[M,N] = A[M,K] * B[N,K]^T (+bias, relu) ----------------
template <bool RELU_BIAS>
__global__ void __launch_bounds__(THREADS, 1)
gemm_tf32_kernel(const float* __restrict__ A, long lda,
                 const float* __restrict__ B, long ldb,
                 float* __restrict__ C, int ldc,
                 int K, const float* __restrict__ bias)
{
    extern __shared__ float sm[];
    const int tid  = threadIdx.x;
    const int lane = tid & 31;
    const int wid  = tid >> 5;
    const int wm   = wid & 3;        // warp m index (0..3), 32 rows each
    const int wn   = wid >> 2;       // warp n index (0..3), 64 cols each
    const int g    = lane >> 2;      // group id (0..7)
    const int tg   = lane & 3;       // thread in group (0..3)
    const long m0  = (long)blockIdx.y * BM;
    const long n0  = (long)blockIdx.x * BN;
    const uint32_t sb = smem_u32(sm);

    // ---- per-thread cp.async source/dest setup ----
    // A tile: 128 rows x 32 floats = 1024 x 16B chunks; thread t does chunks t, t+512
    // B tile: 256 rows x 32 floats = 2048 chunks; thread t does chunks t + j*512, j=0..3
    const int crow = tid >> 3;                  // 0..63
    const int cseg = (tid & 7) * 4;             // float offset of 16B chunk in row
    const float* Ag0 = A + (m0 + crow) * lda + cseg;
    const float* Ag1 = Ag0 + 64 * lda;
    const float* Bg0 = B + (n0 + crow) * ldb + cseg;
    const float* Bg1 = Bg0 + 64 * ldb;
    const float* Bg2 = Bg0 + 128 * ldb;
    const float* Bg3 = Bg0 + 192 * ldb;
    const uint32_t aD = sb + (uint32_t)(crow * AROW + cseg) * 4;
    const uint32_t bD = sb + (uint32_t)(A_ELEMS + crow * AROW + cseg) * 4;

#define ISSUE(s, kt) do {                                                  \
        const uint32_t so = (uint32_t)(s) * (STAGE_ELEMS * 4);             \
        const long ko = (long)(kt) * BK;                                   \
        cp16(aD + so,                 Ag0 + ko);                           \
        cp16(aD + so + 64 * AROW * 4, Ag1 + ko);                           \
        cp16(bD + so,                  Bg0 + ko);                          \
        cp16(bD + so +  64 * AROW * 4, Bg1 + ko);                          \
        cp16(bD + so + 128 * AROW * 4, Bg2 + ko);                          \
        cp16(bD + so + 192 * AROW * 4, Bg3 + ko);                          \
    } while (0)

    const int NITER = K / BK;

#pragma unroll
    for (int s = 0; s < NSTAGE - 1; ++s) {
        ISSUE(s, s);
        asm volatile("cp.async.commit_group;");
    }

    float acc[2][8][4] = {};

    for (int it = 0; it < NITER; ++it) {
        asm volatile("cp.async.wait_group 1;");
        __syncthreads();

        const int ld = it + NSTAGE - 1;
        if (ld < NITER) ISSUE(ld % NSTAGE, ld);
        asm volatile("cp.async.commit_group;");

        const float* As = sm + (it % NSTAGE) * STAGE_ELEMS;
        const float* Bs = As + A_ELEMS;
        const float* Ap = As + (wm * 32 + g) * AROW + tg;
        const float* Bp = Bs + (wn * 64 + g) * AROW + tg;

#pragma unroll
        for (int ks = 0; ks < BK / 8; ++ks) {
            uint32_t af[2][4];
#pragma unroll
            for (int mt = 0; mt < 2; ++mt) {
                const float* p = Ap + mt * 16 * AROW + ks * 8;
                af[mt][0] = f2tf(p[0]);
                af[mt][1] = f2tf(p[8 * AROW]);
                af[mt][2] = f2tf(p[4]);
                af[mt][3] = f2tf(p[8 * AROW + 4]);
            }
            uint32_t bf[8][2];
#pragma unroll
            for (int nt = 0; nt < 8; ++nt) {
                const float* p = Bp + nt * 8 * AROW + ks * 8;
                bf[nt][0] = f2tf(p[0]);
                bf[nt][1] = f2tf(p[4]);
            }
#pragma unroll
            for (int mt = 0; mt < 2; ++mt)
#pragma unroll
                for (int nt = 0; nt < 8; ++nt)
                    mma_tf32(acc[mt][nt], af[mt], bf[nt]);
        }
    }
#undef ISSUE

    // ---- epilogue: direct float2 stores ----
    const long row0 = m0 + wm * 32 + g;
    const int  col0 = (int)n0 + wn * 64 + tg * 2;
#pragma unroll
    for (int mt = 0; mt < 2; ++mt) {
#pragma unroll
        for (int nt = 0; nt < 8; ++nt) {
            const long r = row0 + mt * 16;
            const int  c = col0 + nt * 8;
            float2 v0 = make_float2(acc[mt][nt][0], acc[mt][nt][1]);
            float2 v1 = make_float2(acc[mt][nt][2], acc[mt][nt][3]);
            if (RELU_BIAS) {
                const float2 bv = *reinterpret_cast<const float2*>(bias + c);
                v0.x = fmaxf(v0.x + bv.x, 0.f); v0.y = fmaxf(v0.y + bv.y, 0.f);
                v1.x = fmaxf(v1.x + bv.x, 0.f); v1.y = fmaxf(v1.y + bv.y, 0.f);
            }
            *reinterpret_cast<float2*>(C + r * ldc + c)       = v0;
            *reinterpret_cast<float2*>(C + (r + 8) * ldc + c) = v1;
        }
    }
}

// ---------------- x transpose: [8192, 512] -> [512, 8192] ----------------
__global__ void __launch_bounds__(256) transpose_kernel(const float* __restrict__ in,
                                                        float* __restrict__ out) {
    __shared__ float tile[32][33];
    const int bx = blockIdx.x * 32;   // n (0..511)
    const int by = blockIdx.y * 32;   // k (0..8191)
    const int tx = threadIdx.x;
    const int ty = threadIdx.y;
#pragma unroll
    for (int i = 0; i < 32; i += 8)
        tile[ty + i][tx] = in[(long)(by + ty + i) * DIM + bx + tx];
    __syncthreads();
#pragma unroll
    for (int i = 0; i < 32; i += 8)
        out[(long)(bx + ty + i) * N_NODES + by + tx] = tile[tx][ty + i];
}

// ---------------- launch ----------------
extern "C" void kernel_launch(void* const* d_in, const int* in_sizes, int n_in,
                              void* d_out, int out_size) {
    const float* x   = (const float*)d_in[0];   // [8192, 512]
    const float* adj = (const float*)d_in[1];   // [8192, 8192]
    const float* W   = (const float*)d_in[2];   // [512, 512]
    const float* b   = (const float*)d_in[3];   // [512]
    float* out = (float*)d_out;                 // [8192, 512]

    float *xT, *agg;
    cudaGetSymbolAddress((void**)&xT,  g_xT);
    cudaGetSymbolAddress((void**)&agg, g_agg);

    cudaFuncSetAttribute(gemm_tf32_kernel<false>,
                         cudaFuncAttributeMaxDynamicSharedMemorySize, (int)SMEM_BYTES);
    cudaFuncSetAttribute(gemm_tf32_kernel<true>,
                         cudaFuncAttributeMaxDynamicSharedMemorySize, (int)SMEM_BYTES);

    // 1) xT = x^T
    transpose_kernel<<<dim3(DIM / 32, N_NODES / 32), dim3(32, 8)>>>(x, xT);

    // 2) agg = adj @ x  == adj[M,K] * xT[N,K]^T
    gemm_tf32_kernel<false><<<dim3(DIM / BN, N_NODES / BM), THREADS, SMEM_BYTES>>>(
        adj, (long)N_NODES, xT, (long)N_NODES, agg, DIM, N_NODES, nullptr);

    // 3) out = relu(agg @ W^T + b)  == agg[M,K] * W[N,K]^T
    gemm_tf32_kernel<true><<<dim3(DIM / BN, N_NODES / BM), THREADS, SMEM_BYTES>>>(
        agg, (long)DIM, W, (long)DIM, out, DIM, DIM, b);
}

// round 7
// speedup vs baseline: 1.0120x; 1.0120x over previous
#include <cuda_runtime.h>
#include <cstdint>
#include <cstddef>

#define N_NODES 8192
#define DIM 512

// Scratch (allocation-free: __device__ global)
// z = W @ x^T : [DIM, N_NODES]  (== (x@W^T)^T, K-major operand for the big GEMM)
__device__ float g_z[(size_t)DIM * N_NODES];

// ---------------- config ----------------
constexpr int BM = 128;
constexpr int BN = 256;
constexpr int BK = 32;
constexpr int NSTAGE = 3;
constexpr int THREADS = 512;              // 16 warps: 4 (M) x 4 (N), warp tile 32x64
constexpr int AROW = BK + 4;              // 36 floats/row pad -> conflict-free frag LDS
constexpr int A_ELEMS = BM * AROW;        // 4608 floats
constexpr int B_ELEMS = BN * AROW;        // 9216 floats
constexpr int STAGE_ELEMS = A_ELEMS + B_ELEMS;
constexpr size_t SMEM_BYTES = (size_t)NSTAGE * STAGE_ELEMS * sizeof(float); // 162 KB

// ---------------- helpers ----------------
__device__ __forceinline__ uint32_t smem_u32(const void* p) {
    uint32_t a;
    asm("{ .reg .u64 t; cvta.to.shared.u64 t, %1; cvt.u32.u64 %0, t; }" : "=r"(a) : "l"(p));
    return a;
}
// fp32 -> tf32 round-to-nearest (zero-mean error; truncation would bias ~1e-3 and fail)
__device__ __forceinline__ uint32_t f2tf(float f) {
    uint32_t u;
    asm("cvt.rna.tf32.f32 %0, %1;" : "=r"(u) : "f"(f));
    return u;
}
__device__ __forceinline__ void cp16(uint32_t dst, const float* src) {
    asm volatile("cp.async.cg.shared.global [%0], [%1], 16;" :: "r"(dst), "l"(src));
}
__device__ __forceinline__ void mma_tf32(float* d, const uint32_t* a, const uint32_t* b) {
    asm volatile(
        "mma.sync.aligned.m16n8k8.row.col.f32.tf32.tf32.f32 "
        "{%0,%1,%2,%3}, {%4,%5,%6,%7}, {%8,%9}, {%0,%1,%2,%3};"
        : "+f"(d[0]), "+f"(d[1]), "+f"(d[2]), "+f"(d[3])
        : "r"(a[0]), "r"(a[1]), "r"(a[2]), "r"(a[3]), "r"(b[0]), "r"(b[1]));
}

// ---------------- TF32 GEMM: C[M,N] = A[M,K] * B[N,K]^T (+bias, relu) ----------------
template <bool RELU_BIAS>
__global__ void __launch_bounds__(THREADS, 1)
gemm_tf32_kernel(const float* __restrict__ A, long lda,
                 const float* __restrict__ B, long ldb,
                 float* __restrict__ C, int ldc,
                 int K, const float* __restrict__ bias)
{
    extern __shared__ float sm[];
    const int tid  = threadIdx.x;
    const int lane = tid & 31;
    const int wid  = tid >> 5;
    const int wm   = wid & 3;        // warp m index (0..3), 32 rows each
    const int wn   = wid >> 2;       // warp n index (0..3), 64 cols each
    const int g    = lane >> 2;      // group id (0..7)
    const int tg   = lane & 3;       // thread in group (0..3)
    const long m0  = (long)blockIdx.y * BM;
    const long n0  = (long)blockIdx.x * BN;
    const uint32_t sb = smem_u32(sm);

    // ---- per-thread cp.async source/dest setup ----
    const int crow = tid >> 3;                  // 0..63
    const int cseg = (tid & 7) * 4;             // float offset of 16B chunk in row
    const float* Ag0 = A + (m0 + crow) * lda + cseg;
    const float* Ag1 = Ag0 + 64 * lda;
    const float* Bg0 = B + (n0 + crow) * ldb + cseg;
    const float* Bg1 = Bg0 + 64 * ldb;
    const float* Bg2 = Bg0 + 128 * ldb;
    const float* Bg3 = Bg0 + 192 * ldb;
    const uint32_t aD = sb + (uint32_t)(crow * AROW + cseg) * 4;
    const uint32_t bD = sb + (uint32_t)(A_ELEMS + crow * AROW + cseg) * 4;

#define ISSUE(s, kt) do {                                                  \
        const uint32_t so = (uint32_t)(s) * (STAGE_ELEMS * 4);             \
        const long ko = (long)(kt) * BK;                                   \
        cp16(aD + so,                 Ag0 + ko);                           \
        cp16(aD + so + 64 * AROW * 4, Ag1 + ko);                           \
        cp16(bD + so,                  Bg0 + ko);                          \
        cp16(bD + so +  64 * AROW * 4, Bg1 + ko);                          \
        cp16(bD + so + 128 * AROW * 4, Bg2 + ko);                          \
        cp16(bD + so + 192 * AROW * 4, Bg3 + ko);                          \
    } while (0)

    const int NITER = K / BK;

#pragma unroll
    for (int s = 0; s < NSTAGE - 1; ++s) {
        ISSUE(s, s);
        asm volatile("cp.async.commit_group;");
    }

    float acc[2][8][4] = {};

    for (int it = 0; it < NITER; ++it) {
        asm volatile("cp.async.wait_group 1;");
        __syncthreads();

        const int ld = it + NSTAGE - 1;
        if (ld < NITER) ISSUE(ld % NSTAGE, ld);
        asm volatile("cp.async.commit_group;");

        const float* As = sm + (it % NSTAGE) * STAGE_ELEMS;
        const float* Bs = As + A_ELEMS;
        const float* Ap = As + (wm * 32 + g) * AROW + tg;
        const float* Bp = Bs + (wn * 64 + g) * AROW + tg;

#pragma unroll
        for (int ks = 0; ks < BK / 8; ++ks) {
            uint32_t af[2][4];
#pragma unroll
            for (int mt = 0; mt < 2; ++mt) {
                const float* p = Ap + mt * 16 * AROW + ks * 8;
                af[mt][0] = f2tf(p[0]);
                af[mt][1] = f2tf(p[8 * AROW]);
                af[mt][2] = f2tf(p[4]);
                af[mt][3] = f2tf(p[8 * AROW + 4]);
            }
            uint32_t bf[8][2];
#pragma unroll
            for (int nt = 0; nt < 8; ++nt) {
                const float* p = Bp + nt * 8 * AROW + ks * 8;
                bf[nt][0] = f2tf(p[0]);
                bf[nt][1] = f2tf(p[4]);
            }
#pragma unroll
            for (int mt = 0; mt < 2; ++mt)
#pragma unroll
                for (int nt = 0; nt < 8; ++nt)
                    mma_tf32(acc[mt][nt], af[mt], bf[nt]);
        }
    }
#undef ISSUE

    // ---- epilogue: direct float2 stores ----
    const long row0 = m0 + wm * 32 + g;
    const int  col0 = (int)n0 + wn * 64 + tg * 2;
#pragma unroll
    for (int mt = 0; mt < 2; ++mt) {
#pragma unroll
        for (int nt = 0; nt < 8; ++nt) {
            const long r = row0 + mt * 16;
            const int  c = col0 + nt * 8;
            float2 v0 = make_float2(acc[mt][nt][0], acc[mt][nt][1]);
            float2 v1 = make_float2(acc[mt][nt][2], acc[mt][nt][3]);
            if (RELU_BIAS) {
                const float2 bv = *reinterpret_cast<const float2*>(bias + c);
                v0.x = fmaxf(v0.x + bv.x, 0.f); v0.y = fmaxf(v0.y + bv.y, 0.f);
                v1.x = fmaxf(v1.x + bv.x, 0.f); v1.y = fmaxf(v1.y + bv.y, 0.f);
            }
            *reinterpret_cast<float2*>(C + r * ldc + c)       = v0;
            *reinterpret_cast<float2*>(C + (r + 8) * ldc + c) = v1;
        }
    }
}

// ---------------- launch ----------------
// out = relu(adj @ (x @ W^T) + b)   [associativity: == relu((adj@x)@W^T + b)]
//   step 1: z = W @ x^T       -> z[n,k] = sum_d W[n,d] x[k,d]   : [512, 8192]
//   step 2: out = adj @ z^T   -> out[m,n] = sum_k adj[m,k] z[n,k], + bias, relu
extern "C" void kernel_launch(void* const* d_in, const int* in_sizes, int n_in,
                              void* d_out, int out_size) {
    const float* x   = (const float*)d_in[0];   // [8192, 512]
    const float* adj = (const float*)d_in[1];   // [8192, 8192]
    const float* W   = (const float*)d_in[2];   // [512, 512]
    const float* b   = (const float*)d_in[3];   // [512]
    float* out = (float*)d_out;                 // [8192, 512]

    float* z;
    cudaGetSymbolAddress((void**)&z, g_z);

    cudaFuncSetAttribute(gemm_tf32_kernel<false>,
                         cudaFuncAttributeMaxDynamicSharedMemorySize, (int)SMEM_BYTES);
    cudaFuncSetAttribute(gemm_tf32_kernel<true>,
                         cudaFuncAttributeMaxDynamicSharedMemorySize, (int)SMEM_BYTES);

    // 1) z = W @ x^T : C[M=512, N=8192] = W[512,512] * x[8192,512]^T
    gemm_tf32_kernel<false><<<dim3(N_NODES / BN, DIM / BM), THREADS, SMEM_BYTES>>>(
        W, (long)DIM, x, (long)DIM, z, N_NODES, DIM, nullptr);

    // 2) out = relu(adj @ z^T + b) : C[M=8192, N=512] = adj[8192,8192] * z[512,8192]^T
    gemm_tf32_kernel<true><<<dim3(DIM / BN, N_NODES / BM), THREADS, SMEM_BYTES>>>(
        adj, (long)N_NODES, z, (long)N_NODES, out, DIM, N_NODES, b);
}

// round 11
// speedup vs baseline: 1.0191x; 1.0070x over previous
#include <cuda_runtime.h>
#include <cstdint>
#include <cstddef>

#define N_NODES 8192
#define DIM 512

// Scratch (allocation-free: __device__ global)
// z = W @ x^T : [DIM, N_NODES]  (== (x@W^T)^T, K-major operand for the big GEMM)
__device__ float g_z[(size_t)DIM * N_NODES];

// ---------------- config ----------------
constexpr int BM = 128;
constexpr int BN = 128;
constexpr int BK = 32;
constexpr int NSTAGE = 3;
constexpr int THREADS = 256;              // 8 warps: 4 (M) x 2 (N), warp tile 32x64
constexpr int AROW = BK + 4;              // 36 floats/row pad -> conflict-free frag LDS
constexpr int A_ELEMS = BM * AROW;        // 4608 floats
constexpr int B_ELEMS = BN * AROW;        // 4608 floats
constexpr int STAGE_ELEMS = A_ELEMS + B_ELEMS;     // 9216 floats
constexpr size_t SMEM_BYTES = (size_t)NSTAGE * STAGE_ELEMS * sizeof(float); // 110.6 KB -> 2 CTAs/SM

// ---------------- helpers ----------------
__device__ __forceinline__ uint32_t smem_u32(const void* p) {
    uint32_t a;
    asm("{ .reg .u64 t; cvta.to.shared.u64 t, %1; cvt.u32.u64 %0, t; }" : "=r"(a) : "l"(p));
    return a;
}
// fp32 -> tf32 round-to-nearest (zero-mean error; truncation would bias ~1e-3 and fail)
__device__ __forceinline__ uint32_t f2tf(float f) {
    uint32_t u;
    asm("cvt.rna.tf32.f32 %0, %1;" : "=r"(u) : "f"(f));
    return u;
}
__device__ __forceinline__ void cp16(uint32_t dst, const float* src) {
    asm volatile("cp.async.cg.shared.global [%0], [%1], 16;" :: "r"(dst), "l"(src));
}
__device__ __forceinline__ void mma_tf32(float* d, const uint32_t* a, const uint32_t* b) {
    asm volatile(
        "mma.sync.aligned.m16n8k8.row.col.f32.tf32.tf32.f32 "
        "{%0,%1,%2,%3}, {%4,%5,%6,%7}, {%8,%9}, {%0,%1,%2,%3};"
        : "+f"(d[0]), "+f"(d[1]), "+f"(d[2]), "+f"(d[3])
        : "r"(a[0]), "r"(a[1]), "r"(a[2]), "r"(a[3]), "r"(b[0]), "r"(b[1]));
}

// ---------------- TF32 GEMM: C[M,N] = A[M,K] * B[N,K]^T (+bias, relu) ----------------
// BM=128, BN=128, 256 threads, 2 CTAs/SM for cross-CTA latency hiding.
template <bool RELU_BIAS>
__global__ void __launch_bounds__(THREADS, 2)
gemm_tf32_kernel(const float* __restrict__ A, long lda,
                 const float* __restrict__ B, long ldb,
                 float* __restrict__ C, int ldc,
                 int K, const float* __restrict__ bias)
{
    extern __shared__ float sm[];
    const int tid  = threadIdx.x;
    const int lane = tid & 31;
    const int wid  = tid >> 5;
    const int wm   = wid & 3;        // warp m index (0..3), 32 rows each
    const int wn   = wid >> 2;       // warp n index (0..1), 64 cols each
    const int g    = lane >> 2;      // group id (0..7)
    const int tg   = lane & 3;       // thread in group (0..3)
    const long m0  = (long)blockIdx.y * BM;
    const long n0  = (long)blockIdx.x * BN;
    const uint32_t sb = smem_u32(sm);

    // ---- per-thread cp.async source/dest setup ----
    // A tile: 128 rows x 32 floats = 1024 x 16B chunks; 256 threads -> 4 chunks each
    // B tile: 128 rows x 32 floats -> 4 chunks each
    const int crow = tid >> 3;                  // 0..31
    const int cseg = (tid & 7) * 4;             // float offset of 16B chunk in row
    const float* Ag0 = A + (m0 + crow) * lda + cseg;
    const float* Ag1 = Ag0 + 32 * lda;
    const float* Ag2 = Ag0 + 64 * lda;
    const float* Ag3 = Ag0 + 96 * lda;
    const float* Bg0 = B + (n0 + crow) * ldb + cseg;
    const float* Bg1 = Bg0 + 32 * ldb;
    const float* Bg2 = Bg0 + 64 * ldb;
    const float* Bg3 = Bg0 + 96 * ldb;
    const uint32_t aD = sb + (uint32_t)(crow * AROW + cseg) * 4;
    const uint32_t bD = sb + (uint32_t)(A_ELEMS + crow * AROW + cseg) * 4;

#define ISSUE(s, kt) do {                                                  \
        const uint32_t so = (uint32_t)(s) * (STAGE_ELEMS * 4);             \
        const long ko = (long)(kt) * BK;                                   \
        cp16(aD + so,                 Ag0 + ko);                           \
        cp16(aD + so + 32 * AROW * 4, Ag1 + ko);                           \
        cp16(aD + so + 64 * AROW * 4, Ag2 + ko);                           \
        cp16(aD + so + 96 * AROW * 4, Ag3 + ko);                           \
        cp16(bD + so,                 Bg0 + ko);                           \
        cp16(bD + so + 32 * AROW * 4, Bg1 + ko);                           \
        cp16(bD + so + 64 * AROW * 4, Bg2 + ko);                           \
        cp16(bD + so + 96 * AROW * 4, Bg3 + ko);                           \
    } while (0)

    const int NITER = K / BK;

#pragma unroll
    for (int s = 0; s < NSTAGE - 1; ++s) {
        ISSUE(s, s);
        asm volatile("cp.async.commit_group;");
    }

    float acc[2][8][4] = {};

    for (int it = 0; it < NITER; ++it) {
        asm volatile("cp.async.wait_group 1;");
        __syncthreads();

        const int ld = it + NSTAGE - 1;
        if (ld < NITER) ISSUE(ld % NSTAGE, ld);
        asm volatile("cp.async.commit_group;");

        const float* As = sm + (it % NSTAGE) * STAGE_ELEMS;
        const float* Bs = As + A_ELEMS;
        const float* Ap = As + (wm * 32 + g) * AROW + tg;
        const float* Bp = Bs + (wn * 64 + g) * AROW + tg;

#pragma unroll
        for (int ks = 0; ks < BK / 8; ++ks) {
            uint32_t af[2][4];
#pragma unroll
            for (int mt = 0; mt < 2; ++mt) {
                const float* p = Ap + mt * 16 * AROW + ks * 8;
                af[mt][0] = f2tf(p[0]);
                af[mt][1] = f2tf(p[8 * AROW]);
                af[mt][2] = f2tf(p[4]);
                af[mt][3] = f2tf(p[8 * AROW + 4]);
            }
            uint32_t bf[8][2];
#pragma unroll
            for (int nt = 0; nt < 8; ++nt) {
                const float* p = Bp + nt * 8 * AROW + ks * 8;
                bf[nt][0] = f2tf(p[0]);
                bf[nt][1] = f2tf(p[4]);
            }
#pragma unroll
            for (int mt = 0; mt < 2; ++mt)
#pragma unroll
                for (int nt = 0; nt < 8; ++nt)
                    mma_tf32(acc[mt][nt], af[mt], bf[nt]);
        }
    }
#undef ISSUE

    // ---- epilogue: direct float2 stores ----
    const long row0 = m0 + wm * 32 + g;
    const int  col0 = (int)n0 + wn * 64 + tg * 2;
#pragma unroll
    for (int mt = 0; mt < 2; ++mt) {
#pragma unroll
        for (int nt = 0; nt < 8; ++nt) {
            const long r = row0 + mt * 16;
            const int  c = col0 + nt * 8;
            float2 v0 = make_float2(acc[mt][nt][0], acc[mt][nt][1]);
            float2 v1 = make_float2(acc[mt][nt][2], acc[mt][nt][3]);
            if (RELU_BIAS) {
                const float2 bv = *reinterpret_cast<const float2*>(bias + c);
                v0.x = fmaxf(v0.x + bv.x, 0.f); v0.y = fmaxf(v0.y + bv.y, 0.f);
                v1.x = fmaxf(v1.x + bv.x, 0.f); v1.y = fmaxf(v1.y + bv.y, 0.f);
            }
            *reinterpret_cast<float2*>(C + r * ldc + c)       = v0;
            *reinterpret_cast<float2*>(C + (r + 8) * ldc + c) = v1;
        }
    }
}

// ---------------- launch ----------------
// out = relu(adj @ (x @ W^T) + b)   [associativity: == relu((adj@x)@W^T + b)]
//   step 1: z = W @ x^T       -> z[n,k] = sum_d W[n,d] x[k,d]   : [512, 8192]
//   step 2: out = adj @ z^T   -> out[m,n] = sum_k adj[m,k] z[n,k], + bias, relu
extern "C" void kernel_launch(void* const* d_in, const int* in_sizes, int n_in,
                              void* d_out, int out_size) {
    const float* x   = (const float*)d_in[0];   // [8192, 512]
    const float* adj = (const float*)d_in[1];   // [8192, 8192]
    const float* W   = (const float*)d_in[2];   // [512, 512]
    const float* b   = (const float*)d_in[3];   // [512]
    float* out = (float*)d_out;                 // [8192, 512]

    float* z;
    cudaGetSymbolAddress((void**)&z, g_z);

    cudaFuncSetAttribute(gemm_tf32_kernel<false>,
                         cudaFuncAttributeMaxDynamicSharedMemorySize, (int)SMEM_BYTES);
    cudaFuncSetAttribute(gemm_tf32_kernel<true>,
                         cudaFuncAttributeMaxDynamicSharedMemorySize, (int)SMEM_BYTES);

    // 1) z = W @ x^T : C[M=512, N=8192] = W[512,512] * x[8192,512]^T
    gemm_tf32_kernel<false><<<dim3(N_NODES / BN, DIM / BM), THREADS, SMEM_BYTES>>>(
        W, (long)DIM, x, (long)DIM, z, N_NODES, DIM, nullptr);

    // 2) out = relu(adj @ z^T + b) : C[M=8192, N=512] = adj[8192,8192] * z[512,8192]^T
    gemm_tf32_kernel<true><<<dim3(DIM / BN, N_NODES / BM), THREADS, SMEM_BYTES>>>(
        adj, (long)N_NODES, z, (long)N_NODES, out, DIM, N_NODES, b);
}